// round 3
// baseline (speedup 1.0000x reference)
#include <cuda_runtime.h>
#include <cuda_bf16.h>
#include <math.h>

#define NNODES 49152
#define NEDGES 196608
#define NGRAPH 1024
#define SNODES 48
#define DFEAT  256
#define GD     512
#define NBLK   192      // NNODES / 256

// ---------------- scratch (static __device__: no allocations allowed) ----------------
// Features stored as split bf16 pairs packed 2-per-uint32 (hi = bf16(x), lo = bf16(x - hi)).
__device__ unsigned g_Ah[(size_t)NNODES * 512];   // A [N,1024] bf16-hi  (cols 0:512 mean1, 512:768 x, 768:1024 lap)
__device__ unsigned g_Al[(size_t)NNODES * 512];   // A lo
__device__ unsigned g_Hh[(size_t)NNODES * 256];   // h [N,512] hi
__device__ unsigned g_Hl[(size_t)NNODES * 256];   // h lo
__device__ unsigned g_A2h[(size_t)NGRAPH * 512];  // A2 [B,1024] hi: [pool(mean2) | pool(h)]
__device__ unsigned g_A2l[(size_t)NGRAPH * 512];
__device__ unsigned g_W1h[512 * 512], g_W1l[512 * 512];  // [512,1024] bf16 = [Wl1|Wr1]
__device__ unsigned g_W2h[512 * 512], g_W2l[512 * 512];
__device__ int   g_deg [NNODES];
__device__ int   g_cnt [NNODES];
__device__ int   g_roff[NNODES + 1];
__device__ int   g_coff[NNODES + 1];
__device__ int   g_curr[NNODES];
__device__ int   g_curc[NNODES];
__device__ int   g_rnbr[NEDGES];
__device__ int   g_cnbr[NEDGES];
__device__ float g_rw  [NEDGES];
__device__ float g_dinv[NNODES];
__device__ int   g_bsum[2 * (NBLK + 1)];
__device__ int   g_gcnt[NGRAPH];
__device__ int   g_gcur[NGRAPH];
__device__ int   g_goff[NGRAPH + 1];
__device__ int   g_gsrc[NEDGES];
__device__ float g_gwt [NEDGES];
__device__ int   g_is64;

// ---------------- small helpers ----------------
static __device__ __forceinline__ float4 f4fma(float4 a, float w, float4 b) {
    a.x = fmaf(w, b.x, a.x); a.y = fmaf(w, b.y, a.y);
    a.z = fmaf(w, b.z, a.z); a.w = fmaf(w, b.w, a.w); return a;
}

static __device__ __forceinline__ int edge_at(const int* __restrict__ w, int idx) {
    return g_is64 ? w[2 * idx] : w[idx];
}

// pack two floats into bf16x2 hi, and the bf16x2 of the residuals into lo
static __device__ __forceinline__ unsigned pack_hi_lo(float x, float y, unsigned& lo) {
    __nv_bfloat16 hx = __float2bfloat16(x);
    __nv_bfloat16 hy = __float2bfloat16(y);
    float rx = x - __bfloat162float(hx);
    float ry = y - __bfloat162float(hy);
    __nv_bfloat16 lx = __float2bfloat16(rx);
    __nv_bfloat16 ly = __float2bfloat16(ry);
    lo = (unsigned)__bfloat16_as_ushort(lx) | ((unsigned)__bfloat16_as_ushort(ly) << 16);
    return (unsigned)__bfloat16_as_ushort(hx) | ((unsigned)__bfloat16_as_ushort(hy) << 16);
}

// unpack hi+lo bf16x2 pair back to two fp32
static __device__ __forceinline__ float2 unpk2(unsigned h, unsigned l) {
    __nv_bfloat162 hb = *reinterpret_cast<__nv_bfloat162*>(&h);
    __nv_bfloat162 lb = *reinterpret_cast<__nv_bfloat162*>(&l);
    return make_float2(__bfloat162float(hb.x) + __bfloat162float(lb.x),
                       __bfloat162float(hb.y) + __bfloat162float(lb.y));
}

#define MMA_BF16(c, a0, a1, a2, a3, b0, b1)                                           \
    asm volatile(                                                                      \
        "mma.sync.aligned.m16n8k16.row.col.f32.bf16.bf16.f32 "                         \
        "{%0,%1,%2,%3},{%4,%5,%6,%7},{%8,%9},{%0,%1,%2,%3};"                           \
        : "+f"((c)[0]), "+f"((c)[1]), "+f"((c)[2]), "+f"((c)[3])                       \
        : "r"(a0), "r"(a1), "r"(a2), "r"(a3), "r"(b0), "r"(b1))

// ---------------- CSR build ----------------
__global__ void init_kernel(int* deg, int* cnt, int* curr, int* curc, int* gcnt, int* gcur) {
    int i = blockIdx.x * blockDim.x + threadIdx.x;
    if (i < NNODES) { deg[i] = 0; cnt[i] = 0; curr[i] = 0; curc[i] = 0; }
    if (i < NGRAPH) { gcnt[i] = 0; gcur[i] = 0; }
    if (i == 0) g_is64 = 1;
}

__global__ void detect_kernel(const int* __restrict__ w, int twoE) {
    int i = blockIdx.x * blockDim.x + threadIdx.x;
    if (i < twoE && (i & 1) && w[i] != 0) g_is64 = 0;
}

__global__ void hist_kernel(const int* __restrict__ ew, int E, int* deg, int* cnt, int* gcnt) {
    int e = blockIdx.x * blockDim.x + threadIdx.x;
    if (e >= E) return;
    atomicAdd(&deg[edge_at(ew, e)], 1);
    int c = edge_at(ew, E + e);
    atomicAdd(&cnt[c], 1);
    atomicAdd(&gcnt[c / SNODES], 1);
}

static __device__ __forceinline__ int block_excl_scan256(int v) {
    __shared__ int ws[8];
    int lane = threadIdx.x & 31, wid = threadIdx.x >> 5;
    int x = v;
    #pragma unroll
    for (int o = 1; o < 32; o <<= 1) {
        int y = __shfl_up_sync(0xffffffffu, x, o);
        if (lane >= o) x += y;
    }
    if (lane == 31) ws[wid] = x;
    __syncthreads();
    if (threadIdx.x == 0) {
        int s = 0;
        #pragma unroll
        for (int w = 0; w < 8; ++w) { int t = ws[w]; ws[w] = s; s += t; }
    }
    __syncthreads();
    int r = x - v + ws[wid];
    __syncthreads();
    return r;
}

__global__ void scan_p1(const int* __restrict__ deg, const int* __restrict__ cnt,
                        int* __restrict__ bsum) {
    const int* in = blockIdx.y ? cnt : deg;
    int v = in[blockIdx.x * 256 + threadIdx.x];
    __shared__ int ws[8];
    int lane = threadIdx.x & 31, wid = threadIdx.x >> 5;
    #pragma unroll
    for (int o = 16; o > 0; o >>= 1) v += __shfl_down_sync(0xffffffffu, v, o);
    if (lane == 0) ws[wid] = v;
    __syncthreads();
    if (threadIdx.x == 0) {
        int s = 0;
        #pragma unroll
        for (int w = 0; w < 8; ++w) s += ws[w];
        bsum[blockIdx.y * (NBLK + 1) + blockIdx.x] = s;
    }
}

__global__ void scan_p2(int* __restrict__ bsum) {
    #pragma unroll 1
    for (int row = 0; row < 2; ++row) {
        int t = threadIdx.x;
        int v = (t < NBLK) ? bsum[row * (NBLK + 1) + t] : 0;
        int e = block_excl_scan256(v);
        if (t < NBLK) bsum[row * (NBLK + 1) + t] = e;
        if (t == NBLK - 1) bsum[row * (NBLK + 1) + NBLK] = e + v;
        __syncthreads();
    }
}

__global__ void scan_p3(const int* __restrict__ deg, const int* __restrict__ cnt,
                        const int* __restrict__ bsum,
                        int* __restrict__ roff, int* __restrict__ coff) {
    const int* in = blockIdx.y ? cnt : deg;
    int* out = blockIdx.y ? coff : roff;
    int i = blockIdx.x * 256 + threadIdx.x;
    int v = in[i];
    int e = block_excl_scan256(v) + bsum[blockIdx.y * (NBLK + 1) + blockIdx.x];
    out[i] = e;
    if (i == NNODES - 1) out[NNODES] = bsum[blockIdx.y * (NBLK + 1) + NBLK];
}

// 1024-wide single-block scan for per-graph edge counts
__global__ void scan_graph(const int* __restrict__ gcnt, int* __restrict__ goff) {
    __shared__ int ws[32];
    int t = threadIdx.x, lane = t & 31, wid = t >> 5;
    int v = gcnt[t];
    int x = v;
    #pragma unroll
    for (int o = 1; o < 32; o <<= 1) {
        int y = __shfl_up_sync(0xffffffffu, x, o);
        if (lane >= o) x += y;
    }
    if (lane == 31) ws[wid] = x;
    __syncthreads();
    if (wid == 0) {
        int s = ws[lane];
        #pragma unroll
        for (int o = 1; o < 32; o <<= 1) {
            int y = __shfl_up_sync(0xffffffffu, s, o);
            if (lane >= o) s += y;
        }
        ws[lane] = s;
    }
    __syncthreads();
    int excl = (wid ? ws[wid - 1] : 0) + x - v;
    goff[t] = excl;
    if (t == 1023) goff[NGRAPH] = excl + v;
}

__global__ void dinv_kernel(const int* __restrict__ deg, float* __restrict__ dinv) {
    int i = blockIdx.x * blockDim.x + threadIdx.x;
    if (i < NNODES) {
        int d = deg[i];
        dinv[i] = (d > 0) ? rsqrtf((float)d) : 0.f;
    }
}

__global__ void fill_kernel(const int* __restrict__ ew, int E,
                            const float* __restrict__ dinv,
                            const int* __restrict__ roff, const int* __restrict__ coff,
                            const int* __restrict__ goff, const int* __restrict__ cnt,
                            int* curr, int* curc, int* gcur,
                            int* __restrict__ rnbr, float* __restrict__ rw,
                            int* __restrict__ cnbr,
                            int* __restrict__ gsrc, float* __restrict__ gwt) {
    int e = blockIdx.x * blockDim.x + threadIdx.x;
    if (e >= E) return;
    int r = edge_at(ew, e);
    int c = edge_at(ew, E + e);
    float w = -(dinv[r] * dinv[c]);
    int p = roff[r] + atomicAdd(&curr[r], 1);
    rnbr[p] = c; rw[p] = w;
    int q = coff[c] + atomicAdd(&curc[c], 1);
    cnbr[q] = r;
    int gd = c / SNODES;
    int q2 = goff[gd] + atomicAdd(&gcur[gd], 1);
    gsrc[q2] = r;
    gwt[q2] = 1.0f / ((float)SNODES * (float)cnt[c]);
}

// ---------------- weight preconvert: [Wl | Wr] -> split bf16 [512,1024] ----------------
__global__ void convw_kernel(const float* __restrict__ Wl, const float* __restrict__ Wr,
                             unsigned* __restrict__ Wh, unsigned* __restrict__ Wlo) {
    int i = blockIdx.x * 256 + threadIdx.x;   // u32 index over 512*512
    if (i >= 512 * 512) return;
    int o  = i >> 9;
    int ku = i & 511;
    const float* src = (ku < 256) ? (Wl + (size_t)o * 512 + ku * 2)
                                  : (Wr + (size_t)o * 512 + (ku - 256) * 2);
    unsigned lo;
    unsigned hi = pack_hi_lo(src[0], src[1], lo);
    Wh[i] = hi; Wlo[i] = lo;
}

// ---------------- lap + concat: writes x -> A cols 512:768, lap_x -> 768:1024 (split pairs) ----------------
__global__ void lap_kernel(const float* __restrict__ x,
                           const int* __restrict__ roff,
                           const int* __restrict__ rnbr,
                           const float* __restrict__ rw,
                           unsigned* __restrict__ Ah, unsigned* __restrict__ Al) {
    int gw   = (blockIdx.x * blockDim.x + threadIdx.x) >> 5;
    int lane = threadIdx.x & 31;
    if (gw >= NNODES) return;
    const float4* xi = (const float4*)(x + (size_t)gw * DFEAT);
    float4 a0 = xi[lane], a1 = xi[lane + 32];
    float4 s0 = a0, s1 = a1;
    int e = roff[gw], end = roff[gw + 1];
    for (; e < end; ++e) {
        int   c = rnbr[e];
        float w = rw[e];
        const float4* xc = (const float4*)(x + (size_t)c * DFEAT);
        s0 = f4fma(s0, w, xc[lane]);
        s1 = f4fma(s1, w, xc[lane + 32]);
    }
    uint2* ph = (uint2*)(Ah + (size_t)gw * 512);
    uint2* pl = (uint2*)(Al + (size_t)gw * 512);
    unsigned l0, l1;
    uint2 h, l;
    h.x = pack_hi_lo(a0.x, a0.y, l0); h.y = pack_hi_lo(a0.z, a0.w, l1); l.x = l0; l.y = l1;
    ph[128 + lane] = h; pl[128 + lane] = l;
    h.x = pack_hi_lo(a1.x, a1.y, l0); h.y = pack_hi_lo(a1.z, a1.w, l1); l.x = l0; l.y = l1;
    ph[160 + lane] = h; pl[160 + lane] = l;
    h.x = pack_hi_lo(s0.x, s0.y, l0); h.y = pack_hi_lo(s0.z, s0.w, l1); l.x = l0; l.y = l1;
    ph[192 + lane] = h; pl[192 + lane] = l;
    h.x = pack_hi_lo(s1.x, s1.y, l0); h.y = pack_hi_lo(s1.z, s1.w, l1); l.x = l0; l.y = l1;
    ph[224 + lane] = h; pl[224 + lane] = l;
}

// ---------------- conv1 mean aggregation: reads A cols 512:1024, writes mean -> cols 0:512 ----------------
__global__ void agg1_kernel(unsigned* __restrict__ Ah, unsigned* __restrict__ Al,
                            const int* __restrict__ coff, const int* __restrict__ cnbr) {
    int gw   = (blockIdx.x * blockDim.x + threadIdx.x) >> 5;
    int lane = threadIdx.x & 31;
    if (gw >= NNODES) return;
    float acc[16];
    #pragma unroll
    for (int i = 0; i < 16; ++i) acc[i] = 0.f;
    const uint4* ph = (const uint4*)Ah;   // 128 uint4 per row
    const uint4* pl = (const uint4*)Al;
    int beg = coff[gw], end = coff[gw + 1];
    for (int e = beg; e < end; ++e) {
        size_t base = (size_t)cnbr[e] * 128;
        uint4 h0 = ph[base + 64 + lane], l0 = pl[base + 64 + lane];
        uint4 h1 = ph[base + 96 + lane], l1 = pl[base + 96 + lane];
        float2 f;
        f = unpk2(h0.x, l0.x); acc[0] += f.x; acc[1] += f.y;
        f = unpk2(h0.y, l0.y); acc[2] += f.x; acc[3] += f.y;
        f = unpk2(h0.z, l0.z); acc[4] += f.x; acc[5] += f.y;
        f = unpk2(h0.w, l0.w); acc[6] += f.x; acc[7] += f.y;
        f = unpk2(h1.x, l1.x); acc[8]  += f.x; acc[9]  += f.y;
        f = unpk2(h1.y, l1.y); acc[10] += f.x; acc[11] += f.y;
        f = unpk2(h1.z, l1.z); acc[12] += f.x; acc[13] += f.y;
        f = unpk2(h1.w, l1.w); acc[14] += f.x; acc[15] += f.y;
    }
    int cnt = end - beg;
    float sc = 1.f / (float)(cnt > 0 ? cnt : 1);
    #pragma unroll
    for (int i = 0; i < 16; ++i) acc[i] *= sc;
    uint4 oh, ol;
    oh.x = pack_hi_lo(acc[0], acc[1], ol.x);
    oh.y = pack_hi_lo(acc[2], acc[3], ol.y);
    oh.z = pack_hi_lo(acc[4], acc[5], ol.z);
    oh.w = pack_hi_lo(acc[6], acc[7], ol.w);
    ((uint4*)Ah)[(size_t)gw * 128 + lane] = oh;
    ((uint4*)Al)[(size_t)gw * 128 + lane] = ol;
    oh.x = pack_hi_lo(acc[8],  acc[9],  ol.x);
    oh.y = pack_hi_lo(acc[10], acc[11], ol.y);
    oh.z = pack_hi_lo(acc[12], acc[13], ol.z);
    oh.w = pack_hi_lo(acc[14], acc[15], ol.w);
    ((uint4*)Ah)[(size_t)gw * 128 + 32 + lane] = oh;
    ((uint4*)Al)[(size_t)gw * 128 + 32 + lane] = ol;
}

// ---------------- tensor-core GEMM on pre-split bf16 inputs ----------------
// C[M,512] = (Ah+Al)[M,1024] @ (Bh+Bl)[512,1024]^T + bias; 3-term MMA (hh+hl+lh).
template <bool GELU, bool SPLIT>
__global__ void __launch_bounds__(256) gemm_mma(
    const unsigned* __restrict__ Ah, const unsigned* __restrict__ Al,
    const unsigned* __restrict__ Bh, const unsigned* __restrict__ Bl,
    const float* __restrict__ bias,
    float* __restrict__ C, unsigned* __restrict__ Ch, unsigned* __restrict__ Cl) {
    __shared__ unsigned sm[2][4][128 * 8];

    const int t    = threadIdx.x;
    const int bm   = blockIdx.y * 128, bn = blockIdx.x * 128;
    const int lane = t & 31, warp = t >> 5;
    const int wm   = warp & 3, wn = warp >> 2;
    const int g    = lane >> 2, tq = lane & 3;
    const int ar   = t >> 2, c4 = t & 3;

    float acc[2][8][4];
    #pragma unroll
    for (int i = 0; i < 2; ++i)
        #pragma unroll
        for (int j = 0; j < 8; ++j)
            #pragma unroll
            for (int q = 0; q < 4; ++q) acc[i][j][q] = 0.f;

    // uint2 = 4 bf16 = k-span 4
    const uint2* pAh = (const uint2*)Ah;
    const uint2* pAl = (const uint2*)Al;
    const uint2* pBh = (const uint2*)Bh;
    const uint2* pBl = (const uint2*)Bl;
    const size_t a0b = (size_t)(bm + ar) * 256 + c4;
    const size_t a1b = (size_t)(bm + ar + 64) * 256 + c4;
    const size_t b0b = (size_t)(bn + ar) * 256 + c4;
    const size_t b1b = (size_t)(bn + ar + 64) * 256 + c4;

    uint2 rA0h, rA1h, rA0l, rA1l, rB0h, rB1h, rB0l, rB1l;

    auto load = [&](int k0) {
        int ko = k0 >> 2;
        rA0h = pAh[a0b + ko]; rA1h = pAh[a1b + ko];
        rA0l = pAl[a0b + ko]; rA1l = pAl[a1b + ko];
        rB0h = pBh[b0b + ko]; rB1h = pBh[b1b + ko];
        rB0l = pBl[b0b + ko]; rB1l = pBl[b1b + ko];
    };

    const int i00 = ar * 8 + (c4 & 1) * 4 + (c4 >> 1);
    const int i01 = i00 + 2;

    auto store = [&](int buf) {
        unsigned* sAh = sm[buf][0]; unsigned* sAl = sm[buf][1];
        unsigned* sBh = sm[buf][2]; unsigned* sBl = sm[buf][3];
        sAh[i00] = rA0h.x; sAh[i01] = rA0h.y; sAh[i00 + 512] = rA1h.x; sAh[i01 + 512] = rA1h.y;
        sAl[i00] = rA0l.x; sAl[i01] = rA0l.y; sAl[i00 + 512] = rA1l.x; sAl[i01 + 512] = rA1l.y;
        sBh[i00] = rB0h.x; sBh[i01] = rB0h.y; sBh[i00 + 512] = rB1h.x; sBh[i01 + 512] = rB1h.y;
        sBl[i00] = rB0l.x; sBl[i01] = rB0l.y; sBl[i00 + 512] = rB1l.x; sBl[i01 + 512] = rB1l.y;
    };

    auto compute = [&](int buf) {
        const uint2* sAh = (const uint2*)sm[buf][0];
        const uint2* sAl = (const uint2*)sm[buf][1];
        const uint2* sBh = (const uint2*)sm[buf][2];
        const uint2* sBl = (const uint2*)sm[buf][3];
        uint2 bh[8], bl[8];
        #pragma unroll
        for (int nt = 0; nt < 8; ++nt) {
            int n = wn * 64 + nt * 8 + g;
            bh[nt] = sBh[n * 4 + tq];
            bl[nt] = sBl[n * 4 + tq];
        }
        #pragma unroll
        for (int mt = 0; mt < 2; ++mt) {
            int m = wm * 32 + mt * 16 + g;
            uint2 ah0 = sAh[m * 4 + tq], ah1 = sAh[(m + 8) * 4 + tq];
            uint2 al0 = sAl[m * 4 + tq], al1 = sAl[(m + 8) * 4 + tq];
            #pragma unroll
            for (int nt = 0; nt < 8; ++nt) {
                MMA_BF16(acc[mt][nt], ah0.x, ah1.x, ah0.y, ah1.y, bh[nt].x, bh[nt].y);
                MMA_BF16(acc[mt][nt], ah0.x, ah1.x, ah0.y, ah1.y, bl[nt].x, bl[nt].y);
                MMA_BF16(acc[mt][nt], al0.x, al1.x, al0.y, al1.y, bh[nt].x, bh[nt].y);
            }
        }
    };

    load(0);
    store(0);
    #pragma unroll 1
    for (int s = 0; s < 64; ++s) {
        __syncthreads();
        if (s < 63) load((s + 1) * 16);
        compute(s & 1);
        if (s < 63) store((s + 1) & 1);
    }

    #pragma unroll
    for (int mt = 0; mt < 2; ++mt) {
        int r0 = bm + wm * 32 + mt * 16 + g;
        #pragma unroll
        for (int nt = 0; nt < 8; ++nt) {
            int cc = bn + wn * 64 + nt * 8 + tq * 2;
            float b0v = bias[cc], b1v = bias[cc + 1];
            float v0 = acc[mt][nt][0] + b0v;
            float v1 = acc[mt][nt][1] + b1v;
            float v2 = acc[mt][nt][2] + b0v;
            float v3 = acc[mt][nt][3] + b1v;
            if (GELU) {
                v0 = 0.5f * v0 * (1.0f + erff(v0 * 0.70710678118654752f));
                v1 = 0.5f * v1 * (1.0f + erff(v1 * 0.70710678118654752f));
                v2 = 0.5f * v2 * (1.0f + erff(v2 * 0.70710678118654752f));
                v3 = 0.5f * v3 * (1.0f + erff(v3 * 0.70710678118654752f));
            }
            if (SPLIT) {
                unsigned lo;
                unsigned hi = pack_hi_lo(v0, v1, lo);
                Ch[(size_t)r0 * 256 + (cc >> 1)] = hi;
                Cl[(size_t)r0 * 256 + (cc >> 1)] = lo;
                hi = pack_hi_lo(v2, v3, lo);
                Ch[(size_t)(r0 + 8) * 256 + (cc >> 1)] = hi;
                Cl[(size_t)(r0 + 8) * 256 + (cc >> 1)] = lo;
            } else {
                *(float2*)(C + (size_t)r0 * GD + cc)       = make_float2(v0, v1);
                *(float2*)(C + (size_t)(r0 + 8) * GD + cc) = make_float2(v2, v3);
            }
        }
    }
}

// ---------------- fused conv2-aggregation + pooling ----------------
// A2[g] = [ (1/S) sum_{i in g} mean_{j->i} h_j  |  (1/S) sum_{i in g} h_i ]
// first term computed edge-wise via graph-grouped CSR with weight 1/(S*cnt_dst).
__global__ void graphagg_kernel(const unsigned* __restrict__ Hh, const unsigned* __restrict__ Hl,
                                const int* __restrict__ goff, const int* __restrict__ gsrc,
                                const float* __restrict__ gwt,
                                unsigned* __restrict__ A2h, unsigned* __restrict__ A2l) {
    int gidx = blockIdx.x;
    int t = threadIdx.x;     // 256 threads; thread handles cols 2t, 2t+1
    float acc0 = 0.f, acc1 = 0.f, p0 = 0.f, p1 = 0.f;
    int beg = goff[gidx], end = goff[gidx + 1];
    for (int e = beg; e < end; ++e) {
        int src = gsrc[e];
        float w = gwt[e];
        float2 f = unpk2(Hh[(size_t)src * 256 + t], Hl[(size_t)src * 256 + t]);
        acc0 = fmaf(w, f.x, acc0);
        acc1 = fmaf(w, f.y, acc1);
    }
    size_t base = (size_t)gidx * SNODES * 256 + t;
    #pragma unroll 4
    for (int s = 0; s < SNODES; ++s) {
        float2 f = unpk2(Hh[base + (size_t)s * 256], Hl[base + (size_t)s * 256]);
        p0 += f.x; p1 += f.y;
    }
    const float inv = 1.0f / (float)SNODES;
    unsigned lo;
    unsigned hi = pack_hi_lo(acc0, acc1, lo);
    A2h[(size_t)gidx * 512 + t] = hi;
    A2l[(size_t)gidx * 512 + t] = lo;
    hi = pack_hi_lo(p0 * inv, p1 * inv, lo);
    A2h[(size_t)gidx * 512 + 256 + t] = hi;
    A2l[(size_t)gidx * 512 + 256 + t] = lo;
}

// ---------------- launcher ----------------
extern "C" void kernel_launch(void* const* d_in, const int* in_sizes, int n_in,
                              void* d_out, int out_size) {
    const float* x   = (const float*)d_in[0];
    const int*   ew  = (const int*)  d_in[1];
    const float* Wl1 = (const float*)d_in[2];
    const float* Wr1 = (const float*)d_in[3];
    const float* b1  = (const float*)d_in[4];
    const float* Wl2 = (const float*)d_in[5];
    const float* Wr2 = (const float*)d_in[6];
    const float* b2  = (const float*)d_in[7];
    int E = in_sizes[1] / 2;

    unsigned *Ah, *Al, *Hh, *Hl, *A2h, *A2l, *W1h, *W1l, *W2h, *W2l;
    float *rw, *dinv, *gwt;
    int *deg, *cnt, *roff, *coff, *curr, *curc, *rnbr, *cnbr, *bsum;
    int *gcnt, *gcur, *goff, *gsrc;
    cudaGetSymbolAddress((void**)&Ah,   g_Ah);
    cudaGetSymbolAddress((void**)&Al,   g_Al);
    cudaGetSymbolAddress((void**)&Hh,   g_Hh);
    cudaGetSymbolAddress((void**)&Hl,   g_Hl);
    cudaGetSymbolAddress((void**)&A2h,  g_A2h);
    cudaGetSymbolAddress((void**)&A2l,  g_A2l);
    cudaGetSymbolAddress((void**)&W1h,  g_W1h);
    cudaGetSymbolAddress((void**)&W1l,  g_W1l);
    cudaGetSymbolAddress((void**)&W2h,  g_W2h);
    cudaGetSymbolAddress((void**)&W2l,  g_W2l);
    cudaGetSymbolAddress((void**)&rw,   g_rw);
    cudaGetSymbolAddress((void**)&dinv, g_dinv);
    cudaGetSymbolAddress((void**)&deg,  g_deg);
    cudaGetSymbolAddress((void**)&cnt,  g_cnt);
    cudaGetSymbolAddress((void**)&roff, g_roff);
    cudaGetSymbolAddress((void**)&coff, g_coff);
    cudaGetSymbolAddress((void**)&curr, g_curr);
    cudaGetSymbolAddress((void**)&curc, g_curc);
    cudaGetSymbolAddress((void**)&rnbr, g_rnbr);
    cudaGetSymbolAddress((void**)&cnbr, g_cnbr);
    cudaGetSymbolAddress((void**)&bsum, g_bsum);
    cudaGetSymbolAddress((void**)&gcnt, g_gcnt);
    cudaGetSymbolAddress((void**)&gcur, g_gcur);
    cudaGetSymbolAddress((void**)&goff, g_goff);
    cudaGetSymbolAddress((void**)&gsrc, g_gsrc);
    cudaGetSymbolAddress((void**)&gwt,  g_gwt);

    int eb = (E + 255) / 256;

    init_kernel<<<(NNODES + 255) / 256, 256>>>(deg, cnt, curr, curc, gcnt, gcur);
    detect_kernel<<<(2 * E + 255) / 256, 256>>>(ew, 2 * E);
    hist_kernel<<<eb, 256>>>(ew, E, deg, cnt, gcnt);
    scan_p1<<<dim3(NBLK, 2), 256>>>(deg, cnt, bsum);
    scan_p2<<<1, 256>>>(bsum);
    scan_p3<<<dim3(NBLK, 2), 256>>>(deg, cnt, bsum, roff, coff);
    scan_graph<<<1, 1024>>>(gcnt, goff);
    dinv_kernel<<<(NNODES + 255) / 256, 256>>>(deg, dinv);
    fill_kernel<<<eb, 256>>>(ew, E, dinv, roff, coff, goff, cnt,
                             curr, curc, gcur, rnbr, rw, cnbr, gsrc, gwt);

    // weight preconversion (cheap, deterministic per launch)
    convw_kernel<<<1024, 256>>>(Wl1, Wr1, W1h, W1l);
    convw_kernel<<<1024, 256>>>(Wl2, Wr2, W2h, W2l);

    // lap + concat -> A[:,512:1024] (split bf16)
    lap_kernel<<<NNODES / 8, 256>>>(x, roff, rnbr, rw, Ah, Al);
    // conv1 mean aggregation -> A[:,0:512]
    agg1_kernel<<<NNODES / 8, 256>>>(Ah, Al, coff, cnbr);
    // conv1 GEMM + bias + exact GELU -> h (split bf16)
    gemm_mma<true, true><<<dim3(4, NNODES / 128), 256>>>(
        Ah, Al, W1h, W1l, b1, nullptr, Hh, Hl);
    // fused conv2-aggregation + pooling -> A2 (split bf16)
    graphagg_kernel<<<NGRAPH, 256>>>(Hh, Hl, goff, gsrc, gwt, A2h, A2l);
    // conv2 GEMM + bias -> out [1024, 512] fp32
    gemm_mma<false, false><<<dim3(4, NGRAPH / 128), 256>>>(
        A2h, A2l, W2h, W2l, b2, (float*)d_out, nullptr, nullptr);
}